// round 2
// baseline (speedup 1.0000x reference)
#include <cuda_runtime.h>

#define H 4096
#define NUM_LAYERS 8
#define ROWS_PER_BLOCK 4
#define THREADS (ROWS_PER_BLOCK * 32)   // one warp per row

// Ping-pong hidden-state buffers (allocation-free scratch).
__device__ float g_h[2][H];

// GEMV: out[row] = act( dot(W[row, :], h_in) + b0[row] (+ b1[row]) )
// W row-major [H, H]; one warp per output row; h_in staged in smem.
// Inner loop unrolled x4 with independent accumulators so 4 LDG.128
// stay in flight per warp (MLP=4) -> hides loaded DRAM latency.
template <bool TANH, bool HAS_B1>
__global__ void __launch_bounds__(THREADS)
gemv_kernel(const float* __restrict__ W,
            const float* __restrict__ b0,
            const float* __restrict__ b1,
            const float* __restrict__ h_in,
            float* __restrict__ h_out) {
    __shared__ float4 sh4[H / 4];

    // Cooperative load of the input vector (16 KB) into shared memory.
    const float4* hv_g = reinterpret_cast<const float4*>(h_in);
    #pragma unroll
    for (int i = threadIdx.x; i < H / 4; i += THREADS)
        sh4[i] = hv_g[i];
    __syncthreads();

    const int warp = threadIdx.x >> 5;
    const int lane = threadIdx.x & 31;
    const int row  = blockIdx.x * ROWS_PER_BLOCK + warp;

    const float4* Wr = reinterpret_cast<const float4*>(W + (size_t)row * H);

    // 1024 float4 per row, 32 per lane, processed in groups of 4.
    float acc[4] = {0.f, 0.f, 0.f, 0.f};
    #pragma unroll
    for (int i = 0; i < 32; i += 4) {
        float4 w[4];
        float4 x[4];
        #pragma unroll
        for (int j = 0; j < 4; j++)
            w[j] = __ldcs(&Wr[lane + (i + j) * 32]);   // evict-first: streamed once
        #pragma unroll
        for (int j = 0; j < 4; j++)
            x[j] = sh4[lane + (i + j) * 32];
        #pragma unroll
        for (int j = 0; j < 4; j++)
            acc[j] += w[j].x * x[j].x + w[j].y * x[j].y
                    + w[j].z * x[j].z + w[j].w * x[j].w;
    }
    float acc_all = (acc[0] + acc[1]) + (acc[2] + acc[3]);

    #pragma unroll
    for (int off = 16; off; off >>= 1)
        acc_all += __shfl_down_sync(0xffffffffu, acc_all, off);

    if (lane == 0) {
        float v = acc_all + b0[row];
        if (HAS_B1) v += b1[row];
        h_out[row] = TANH ? tanhf(v) : v;
    }
}

extern "C" void kernel_launch(void* const* d_in, const int* in_sizes, int n_in,
                              void* d_out, int out_size) {
    const float* x    = (const float*)d_in[0];  // [1, H]
    const float* Wxh  = (const float*)d_in[1];  // [L, H, H]
    const float* bxh  = (const float*)d_in[2];  // [L, H]
    // d_in[3] = Whh — multiplied by a zero vector in the reference; never read.
    const float* bhh  = (const float*)d_in[4];  // [L, H]
    const float* fc_w = (const float*)d_in[5];  // [H, H]
    const float* fc_b = (const float*)d_in[6];  // [H]
    float* out = (float*)d_out;

    float* hbuf = nullptr;
    cudaGetSymbolAddress((void**)&hbuf, g_h);
    float* h0 = hbuf;      // g_h[0]
    float* h1 = hbuf + H;  // g_h[1]

    const dim3 grid(H / ROWS_PER_BLOCK);  // 1024 blocks
    const dim3 block(THREADS);            // 128 threads

    const float* cur = x;
    float* nxt = h0;
    for (int i = 0; i < NUM_LAYERS; i++) {
        gemv_kernel<true, true><<<grid, block>>>(
            Wxh + (size_t)i * H * H, bxh + (size_t)i * H, bhh + (size_t)i * H,
            cur, nxt);
        cur = nxt;
        nxt = (nxt == h0) ? h1 : h0;
    }
    // Final linear layer: no tanh, single bias.
    gemv_kernel<false, false><<<grid, block>>>(fc_w, fc_b, nullptr, cur, out);
}

// round 3
// speedup vs baseline: 1.0380x; 1.0380x over previous
#include <cuda_runtime.h>

#define H 4096
#define NUM_LAYERS 8
#define ROWS_PER_BLOCK 4
#define SPLIT_K 2
#define WARPS_PER_BLOCK (ROWS_PER_BLOCK * SPLIT_K)   // 8
#define THREADS (WARPS_PER_BLOCK * 32)               // 256
#define COLS_PER_WARP (H / SPLIT_K)                  // 2048 floats
#define F4_PER_LANE (COLS_PER_WARP / 4 / 32)         // 16 float4

// Ping-pong hidden-state buffers (allocation-free scratch).
__device__ float g_h[2][H];

// GEMV with split-K=2: two warps per output row, each covering half the row.
// Doubles resident warps (grid-bound occupancy) to hide DRAM latency.
template <bool TANH, bool HAS_B1>
__global__ void __launch_bounds__(THREADS)
gemv_kernel(const float* __restrict__ W,
            const float* __restrict__ b0,
            const float* __restrict__ b1,
            const float* __restrict__ h_in,
            float* __restrict__ h_out) {
    __shared__ float4 sh4[H / 4];
    __shared__ float partial[WARPS_PER_BLOCK];

    // Cooperative load of the input vector (16 KB) into shared memory.
    const float4* hv_g = reinterpret_cast<const float4*>(h_in);
    #pragma unroll
    for (int i = threadIdx.x; i < H / 4; i += THREADS)
        sh4[i] = hv_g[i];
    __syncthreads();

    const int warp = threadIdx.x >> 5;
    const int lane = threadIdx.x & 31;
    const int row  = blockIdx.x * ROWS_PER_BLOCK + (warp >> 1);
    const int half = warp & 1;

    // This warp's half-row: 2048 floats = 512 float4, 16 per lane.
    const float4* Wr = reinterpret_cast<const float4*>(W + (size_t)row * H) +
                       half * (COLS_PER_WARP / 4);
    const float4* xh = sh4 + half * (COLS_PER_WARP / 4);

    float acc[4] = {0.f, 0.f, 0.f, 0.f};
    #pragma unroll
    for (int i = 0; i < F4_PER_LANE; i += 4) {
        float4 w[4], x[4];
        #pragma unroll
        for (int j = 0; j < 4; j++)
            w[j] = Wr[lane + (i + j) * 32];
        #pragma unroll
        for (int j = 0; j < 4; j++)
            x[j] = xh[lane + (i + j) * 32];
        #pragma unroll
        for (int j = 0; j < 4; j++)
            acc[j] += w[j].x * x[j].x + w[j].y * x[j].y
                    + w[j].z * x[j].z + w[j].w * x[j].w;
    }
    float acc_all = (acc[0] + acc[1]) + (acc[2] + acc[3]);

    #pragma unroll
    for (int off = 16; off; off >>= 1)
        acc_all += __shfl_down_sync(0xffffffffu, acc_all, off);

    if (lane == 0)
        partial[warp] = acc_all;
    __syncthreads();

    // One thread per row combines the two half-row partials (deterministic).
    if (threadIdx.x < ROWS_PER_BLOCK) {
        const int r = blockIdx.x * ROWS_PER_BLOCK + threadIdx.x;
        float v = partial[2 * threadIdx.x] + partial[2 * threadIdx.x + 1] + b0[r];
        if (HAS_B1) v += b1[r];
        h_out[r] = TANH ? tanhf(v) : v;
    }
}

extern "C" void kernel_launch(void* const* d_in, const int* in_sizes, int n_in,
                              void* d_out, int out_size) {
    const float* x    = (const float*)d_in[0];  // [1, H]
    const float* Wxh  = (const float*)d_in[1];  // [L, H, H]
    const float* bxh  = (const float*)d_in[2];  // [L, H]
    // d_in[3] = Whh — multiplied by a zero vector in the reference; never read.
    const float* bhh  = (const float*)d_in[4];  // [L, H]
    const float* fc_w = (const float*)d_in[5];  // [H, H]
    const float* fc_b = (const float*)d_in[6];  // [H]
    float* out = (float*)d_out;

    float* hbuf = nullptr;
    cudaGetSymbolAddress((void**)&hbuf, g_h);
    float* h0 = hbuf;      // g_h[0]
    float* h1 = hbuf + H;  // g_h[1]

    const dim3 grid(H / ROWS_PER_BLOCK);  // 1024 blocks
    const dim3 block(THREADS);            // 256 threads (8 warps)

    const float* cur = x;
    float* nxt = h0;
    for (int i = 0; i < NUM_LAYERS; i++) {
        gemv_kernel<true, true><<<grid, block>>>(
            Wxh + (size_t)i * H * H, bxh + (size_t)i * H, bhh + (size_t)i * H,
            cur, nxt);
        cur = nxt;
        nxt = (nxt == h0) ? h1 : h0;
    }
    // Final linear layer: no tanh, single bias.
    gemv_kernel<false, false><<<grid, block>>>(fc_w, fc_b, nullptr, cur, out);
}

// round 4
// speedup vs baseline: 1.1461x; 1.1041x over previous
#include <cuda_runtime.h>

#define H 4096
#define NUM_LAYERS 8
#define WARPS_PER_BLOCK 8
#define THREADS (WARPS_PER_BLOCK * 32)
#define ROWS_PER_BLOCK WARPS_PER_BLOCK
#define F4_PER_LANE 32          // 1024 float4 per row / 32 lanes
#define BATCH 8                 // LDG.128s front-batched per warp

// Ping-pong hidden-state buffers (allocation-free scratch).
__device__ float g_h[2][H];

// GEMV: out[row] = act( dot(W[row, :], h_in) + b0[row] (+ b1[row]) )
// One warp per output row. Weight loads issued in dependence-free batches
// of 8 LDG.128 so ~4KB/warp stays in flight (DRAM latency hiding), with the
// batch loop fully unrolled so ptxas pipelines load batch b+1 over FMA batch b.
template <bool TANH, bool HAS_B1>
__global__ void __launch_bounds__(THREADS, 2)
gemv_kernel(const float* __restrict__ W,
            const float* __restrict__ b0,
            const float* __restrict__ b1,
            const float* __restrict__ h_in,
            float* __restrict__ h_out) {
    __shared__ float4 sh4[H / 4];

    // Cooperative load of the input vector (16 KB) into shared memory.
    const float4* hv_g = reinterpret_cast<const float4*>(h_in);
    #pragma unroll
    for (int i = threadIdx.x; i < H / 4; i += THREADS)
        sh4[i] = hv_g[i];
    __syncthreads();

    const int warp = threadIdx.x >> 5;
    const int lane = threadIdx.x & 31;
    const int row  = blockIdx.x * ROWS_PER_BLOCK + warp;

    const float4* Wr = reinterpret_cast<const float4*>(W + (size_t)row * H);

    float acc[4] = {0.f, 0.f, 0.f, 0.f};
    #pragma unroll
    for (int b = 0; b < F4_PER_LANE / BATCH; b++) {
        // Phase 1: 8 independent LDG.128 — nothing consumes them yet.
        float4 w[BATCH];
        #pragma unroll
        for (int j = 0; j < BATCH; j++)
            w[j] = Wr[lane + (b * BATCH + j) * 32];
        // Phase 2: consume with x from shared memory.
        #pragma unroll
        for (int j = 0; j < BATCH; j++) {
            float4 xv = sh4[lane + (b * BATCH + j) * 32];
            acc[j & 3] += w[j].x * xv.x + w[j].y * xv.y
                        + w[j].z * xv.z + w[j].w * xv.w;
        }
    }
    float acc_all = (acc[0] + acc[1]) + (acc[2] + acc[3]);

    #pragma unroll
    for (int off = 16; off; off >>= 1)
        acc_all += __shfl_down_sync(0xffffffffu, acc_all, off);

    if (lane == 0) {
        float v = acc_all + b0[row];
        if (HAS_B1) v += b1[row];
        h_out[row] = TANH ? tanhf(v) : v;
    }
}

extern "C" void kernel_launch(void* const* d_in, const int* in_sizes, int n_in,
                              void* d_out, int out_size) {
    const float* x    = (const float*)d_in[0];  // [1, H]
    const float* Wxh  = (const float*)d_in[1];  // [L, H, H]
    const float* bxh  = (const float*)d_in[2];  // [L, H]
    // d_in[3] = Whh — multiplied by a zero vector in the reference; never read.
    const float* bhh  = (const float*)d_in[4];  // [L, H]
    const float* fc_w = (const float*)d_in[5];  // [H, H]
    const float* fc_b = (const float*)d_in[6];  // [H]
    float* out = (float*)d_out;

    float* hbuf = nullptr;
    cudaGetSymbolAddress((void**)&hbuf, g_h);
    float* h0 = hbuf;      // g_h[0]
    float* h1 = hbuf + H;  // g_h[1]

    const dim3 grid(H / ROWS_PER_BLOCK);  // 512 blocks
    const dim3 block(THREADS);            // 256 threads

    const float* cur = x;
    float* nxt = h0;
    for (int i = 0; i < NUM_LAYERS; i++) {
        gemv_kernel<true, true><<<grid, block>>>(
            Wxh + (size_t)i * H * H, bxh + (size_t)i * H, bhh + (size_t)i * H,
            cur, nxt);
        cur = nxt;
        nxt = (nxt == h0) ? h1 : h0;
    }
    // Final linear layer: no tanh, single bias.
    gemv_kernel<false, false><<<grid, block>>>(fc_w, fc_b, nullptr, cur, out);
}